// round 16
// baseline (speedup 1.0000x reference)
#include <cuda_runtime.h>
#include <cuda_fp16.h>
#include <mma.h>
#include <cstddef>
#include <cstdint>

using namespace nvcuda;

#define N_NODES   50000
#define N_GRAPHS  128
#define IN_C      128
#define HID_C     128
#define OUT_C     64

// ---------------- device scratch (no allocations allowed) ----------------
// All arrays are zero at module load (BSS). Each kernel_launch call re-zeroes
// every accumulator after its last read ("self-cleaning"), so the zero-at-entry
// invariant holds for every call, making the graph deterministic with no
// explicit init kernel.
__device__ int    g_degi[N_NODES];
__device__ __half g_g1h [(size_t)N_NODES * HID_C];   // fp16 messages L1 (fully overwritten each call)
__device__ __half g_acc1[(size_t)N_NODES * HID_C];   // fp16 scatter accumulator L1
__device__ __half g_g2h [(size_t)N_NODES * OUT_C];   // fp16 messages L2 (fully overwritten each call)
__device__ __half g_acc2[(size_t)N_NODES * OUT_C];   // fp16 scatter accumulator L2
__device__ float  g_gsum[N_GRAPHS * OUT_C];
__device__ float  g_gcnt[N_GRAPHS];

__device__ __forceinline__ float node_dinv(int i) {
    return rsqrtf((float)(1 + g_degi[i]));   // +1 self-loop
}
__device__ __forceinline__ void red_add_v4(float* p, float4 v) {
    asm volatile("red.global.add.v4.f32 [%0], {%1, %2, %3, %4};"
                 :: "l"(p), "f"(v.x), "f"(v.y), "f"(v.z), "f"(v.w)
                 : "memory");
}
// 8 halfs per op (16B) — sm_90+
__device__ __forceinline__ void red_add_v4h(__half* p, uint4 v) {
    asm volatile("red.global.add.noftz.v4.f16x2 [%0], {%1, %2, %3, %4};"
                 :: "l"(p), "r"(v.x), "r"(v.y), "r"(v.z), "r"(v.w)
                 : "memory");
}
__device__ __forceinline__ uint4 f8_to_h8(float4 a, float4 b) {
    __half2 h0 = __floats2half2_rn(a.x, a.y);
    __half2 h1 = __floats2half2_rn(a.z, a.w);
    __half2 h2 = __floats2half2_rn(b.x, b.y);
    __half2 h3 = __floats2half2_rn(b.z, b.w);
    uint4 u;
    u.x = *reinterpret_cast<unsigned*>(&h0);
    u.y = *reinterpret_cast<unsigned*>(&h1);
    u.z = *reinterpret_cast<unsigned*>(&h2);
    u.w = *reinterpret_cast<unsigned*>(&h3);
    return u;
}

// ---------------- degree (by dst); relies on degi==0 at entry ----------------
__global__ void deg_kernel(const int* __restrict__ dst, int E) {
    int e = blockIdx.x * blockDim.x + threadIdx.x;
    if (e < E) atomicAdd(&g_degi[dst[e]], 1);
}

// ---------------- fp16 HMMA GEMM, BM=64: C16 = dinv ⊙ (A[M,128] @ B[128,LD]) ----------------
// 256 threads = 8 warps as 4(m) x 2(n); warp covers 16 rows x LD/2 cols.
// FUSE_IN: A row = relu(dinv*(acc1+g1h)+bias); also ZEROES acc1 after reading
// (self-cleaning — gemm2 is acc1's last reader).
template<int LD, bool FUSE_IN>
__global__ void __launch_bounds__(256)
hgemm_kernel(const float* __restrict__ A,
             const float* __restrict__ bias,
             const float* __restrict__ B,
             __half* __restrict__ C16, int M) {
    extern __shared__ __half sm[];
    constexpr int LDA = 136;          // 128 + 8 pad
    constexpr int LDB = LD + 8;
    constexpr int NT  = LD / 32;      // 16-wide n-tiles per warp
    __half* As = sm;                  // [64][136]
    __half* Bs = sm + 64 * LDA;       // [128][LDB]

    const int tid    = threadIdx.x;
    const int wid    = tid >> 5;
    const int lane   = tid & 31;
    const int warp_m = wid >> 1;      // rows warp_m*16
    const int warp_n = wid & 1;       // cols warp_n*(LD/2)
    const int row0   = blockIdx.x * 64;

    // ---- stage A: 64*128 halfs = 1024 chunks of 8; 4 iters ----
#pragma unroll
    for (int it = 0; it < 4; it++) {
        int chunk = tid + it * 256;
        int r  = chunk >> 4;
        int c8 = chunk & 15;
        int grow = row0 + r;
        uint4 u;
        if (grow < M) {
            if (FUSE_IN) {
                float dv = node_dinv(grow);
                uint4* accp = (uint4*)(g_acc1 + (size_t)grow * 128) + c8;
                uint4 au = *accp;
                *accp = make_uint4(0, 0, 0, 0);        // self-clean acc1
                uint4 gu = ((const uint4*)(g_g1h + (size_t)grow * 128))[c8];
                float4 bv0 = *(const float4*)(bias + c8 * 8);
                float4 bv1 = *(const float4*)(bias + c8 * 8 + 4);
                const __half2* ah = (const __half2*)&au;
                const __half2* gh = (const __half2*)&gu;
                float4 lo, hi;
                float2 t0 = __half22float2(ah[0]), s0 = __half22float2(gh[0]);
                float2 t1 = __half22float2(ah[1]), s1 = __half22float2(gh[1]);
                float2 t2 = __half22float2(ah[2]), s2 = __half22float2(gh[2]);
                float2 t3 = __half22float2(ah[3]), s3 = __half22float2(gh[3]);
                lo.x = fmaxf(dv * (t0.x + s0.x) + bv0.x, 0.f);
                lo.y = fmaxf(dv * (t0.y + s0.y) + bv0.y, 0.f);
                lo.z = fmaxf(dv * (t1.x + s1.x) + bv0.z, 0.f);
                lo.w = fmaxf(dv * (t1.y + s1.y) + bv0.w, 0.f);
                hi.x = fmaxf(dv * (t2.x + s2.x) + bv1.x, 0.f);
                hi.y = fmaxf(dv * (t2.y + s2.y) + bv1.y, 0.f);
                hi.z = fmaxf(dv * (t3.x + s3.x) + bv1.z, 0.f);
                hi.w = fmaxf(dv * (t3.y + s3.y) + bv1.w, 0.f);
                u = f8_to_h8(lo, hi);
            } else {
                float4 lo = *(const float4*)(A + (size_t)grow * 128 + c8 * 8);
                float4 hi = *(const float4*)(A + (size_t)grow * 128 + c8 * 8 + 4);
                u = f8_to_h8(lo, hi);
            }
        } else {
            u = make_uint4(0, 0, 0, 0);
        }
        *(uint4*)(As + r * LDA + c8 * 8) = u;
    }
    // ---- stage B: 128*LD halfs ----
    constexpr int BCH = 128 * LD / 8 / 256;   // 8 (LD=128) or 4 (LD=64)
#pragma unroll
    for (int it = 0; it < BCH; it++) {
        int chunk = tid + it * 256;
        int r  = chunk / (LD / 8);
        int c8 = chunk % (LD / 8);
        float4 lo = *(const float4*)(B + (size_t)r * LD + c8 * 8);
        float4 hi = *(const float4*)(B + (size_t)r * LD + c8 * 8 + 4);
        *(uint4*)(Bs + r * LDB + c8 * 8) = f8_to_h8(lo, hi);
    }
    __syncthreads();

    // ---- MMA: 8 k-steps, 1 m-frag x NT n-frags per warp ----
    wmma::fragment<wmma::accumulator, 16, 16, 16, float> acc[NT];
#pragma unroll
    for (int nt = 0; nt < NT; nt++) wmma::fill_fragment(acc[nt], 0.f);

#pragma unroll
    for (int k = 0; k < 8; k++) {
        wmma::fragment<wmma::matrix_a, 16, 16, 16, __half, wmma::row_major> a0;
        wmma::load_matrix_sync(a0, As + (warp_m * 16) * LDA + k * 16, LDA);
#pragma unroll
        for (int nt = 0; nt < NT; nt++) {
            wmma::fragment<wmma::matrix_b, 16, 16, 16, __half, wmma::row_major> b;
            wmma::load_matrix_sync(b, Bs + (k * 16) * LDB + warp_n * (LD / 2) + nt * 16, LDB);
            wmma::mma_sync(acc[nt], a0, b, acc[nt]);
        }
    }
    __syncthreads();

    // ---- epilogue: per-warp staging (ldm=16 — WMMA contract), dinv, fp16 store ----
    float* wbuf = (float*)(sm) + wid * 256;    // 16x16 floats per warp
#pragma unroll
    for (int nt = 0; nt < NT; nt++) {
        wmma::store_matrix_sync(wbuf, acc[nt], 16, wmma::mem_row_major);
        __syncwarp();
        int r  = lane >> 1;
        int c8 = (lane & 1) * 8;
        int grow = row0 + warp_m * 16 + r;
        if (grow < M) {
            float d = node_dinv(grow);
            const float* p = wbuf + r * 16 + c8;
            float4 lo = make_float4(d * p[0], d * p[1], d * p[2], d * p[3]);
            float4 hi = make_float4(d * p[4], d * p[5], d * p[6], d * p[7]);
            int col = warp_n * (LD / 2) + nt * 16 + c8;
            *(uint4*)(C16 + (size_t)grow * LD + col) = f8_to_h8(lo, hi);
        }
        __syncwarp();
    }
}

// ---------------- scatter layer 1: acc1[dst] += g1h[src] (128 halfs/edge, 16 lanes) ----------------
__global__ void scatter1_kernel(const int* __restrict__ src,
                                const int* __restrict__ dst,
                                int E) {
    int t = blockIdx.x * blockDim.x + threadIdx.x;
    int e = t >> 4;
    int lane = t & 15;
    if (e >= E) return;
    int s = src[e];
    int d = dst[e];
    uint4 v = ((const uint4*)(g_g1h + (size_t)s * HID_C))[lane];  // 8 halfs
    red_add_v4h(g_acc1 + (size_t)d * HID_C + lane * 8, v);
}

// ---------------- scatter layer 2: acc2[dst] += g2h[src] (64 halfs/edge, 8 lanes) ----------------
__global__ void scatter2_kernel(const int* __restrict__ src,
                                const int* __restrict__ dst,
                                int E) {
    int t = blockIdx.x * blockDim.x + threadIdx.x;
    int e = t >> 3;
    int lane = t & 7;
    if (e >= E) return;
    int s = src[e];
    int d = dst[e];
    uint4 v = ((const uint4*)(g_g2h + (size_t)s * OUT_C))[lane];  // 8 halfs
    red_add_v4h(g_acc2 + (size_t)d * OUT_C + lane * 8, v);
}

// ---------------- pool: out2 = dinv*(acc2+g2h)+b2; RED into graph sums ----------------
// Self-cleans acc2 and degi (last reader of both).
__global__ void pool_kernel(const int* __restrict__ batch,
                            const float* __restrict__ b2,
                            int N) {
    int t = blockIdx.x * blockDim.x + threadIdx.x;
    int node = t >> 4;
    int lane = t & 15;
    if (node >= N) return;
    int b = batch[node];
    float dv = node_dinv(node);
    uint2* accp = (uint2*)(g_acc2 + (size_t)node * OUT_C) + lane;
    uint2 au = *accp;
    *accp = make_uint2(0, 0);                 // self-clean acc2 (same thread read->write)
    if (lane == 0) g_degi[node] = 0;          // self-clean degi (warp-ordered after the load above)
    uint2 gu = ((const uint2*)(g_g2h + (size_t)node * OUT_C))[lane];
    __half2 ah0 = *reinterpret_cast<__half2*>(&au.x);
    __half2 ah1 = *reinterpret_cast<__half2*>(&au.y);
    __half2 gh0 = *reinterpret_cast<__half2*>(&gu.x);
    __half2 gh1 = *reinterpret_cast<__half2*>(&gu.y);
    float2 a0 = __half22float2(ah0), a1 = __half22float2(ah1);
    float2 g0 = __half22float2(gh0), g1 = __half22float2(gh1);
    float4 bv = *(const float4*)(b2 + lane * 4);
    float4 r;
    r.x = dv * (a0.x + g0.x) + bv.x;
    r.y = dv * (a0.y + g0.y) + bv.y;
    r.z = dv * (a1.x + g1.x) + bv.z;
    r.w = dv * (a1.y + g1.y) + bv.w;
    red_add_v4(g_gsum + b * OUT_C + lane * 4, r);
    if (lane == 0) atomicAdd(&g_gcnt[b], 1.0f);
}

// ---------------- divide + self-clean gsum/gcnt ----------------
__global__ void divide_kernel(float* __restrict__ out, int G) {
    int i = blockIdx.x * blockDim.x + threadIdx.x;
    float v = 0.f;
    bool act = (i < G * OUT_C);
    if (act) {
        float c = g_gcnt[i / OUT_C];
        v = g_gsum[i] / fmaxf(c, 1.0f);
    }
    __syncthreads();     // all reads of gcnt within this block complete before zeroing
    if (act) {
        out[i] = v;
        g_gsum[i] = 0.f;
        if (i < G) g_gcnt[i] = 0.f;
    }
}

// ---------------- launch ----------------
extern "C" void kernel_launch(void* const* d_in, const int* in_sizes, int n_in,
                              void* d_out, int out_size) {
    const float* x   = (const float*)d_in[0];
    const float* W1  = (const float*)d_in[1];
    const float* b1  = (const float*)d_in[2];
    const float* W2  = (const float*)d_in[3];
    const float* b2  = (const float*)d_in[4];
    const int*   ei  = (const int*)d_in[5];   // int32
    const int*   bat = (const int*)d_in[6];

    const int N = in_sizes[0] / IN_C;      // 50000
    const int E = in_sizes[5] / 2;         // 625000
    const int G = out_size / OUT_C;        // 128

    const int* src = ei;
    const int* dst = ei + E;

    void *p_g1h, *p_g2h;
    cudaGetSymbolAddress(&p_g1h, g_g1h);
    cudaGetSymbolAddress(&p_g2h, g_g2h);

    deg_kernel<<<(E + 255) / 256, 256>>>(dst, E);

    // GEMM1: g1h = dinv * (x @ W1)
    {
        const int smem = (64 * 136 + 128 * (128 + 8)) * (int)sizeof(__half);
        cudaFuncSetAttribute(hgemm_kernel<128, false>,
                             cudaFuncAttributeMaxDynamicSharedMemorySize, smem);
        hgemm_kernel<128, false><<<(N + 63) / 64, 256, smem>>>(
            x, nullptr, W1, (__half*)p_g1h, N);
    }
    scatter1_kernel<<<((size_t)E * 16 + 255) / 256, 256>>>(src, dst, E);

    // GEMM2: g2h = dinv * (relu(dinv*(acc1+g1h)+b1) @ W2)   (+ self-clean acc1)
    {
        const int smem = (64 * 136 + 128 * (64 + 8)) * (int)sizeof(__half);
        cudaFuncSetAttribute(hgemm_kernel<64, true>,
                             cudaFuncAttributeMaxDynamicSharedMemorySize, smem);
        hgemm_kernel<64, true><<<(N + 63) / 64, 256, smem>>>(
            nullptr, b1, W2, (__half*)p_g2h, N);
    }
    scatter2_kernel<<<((size_t)E * 8 + 255) / 256, 256>>>(src, dst, E);

    pool_kernel<<<(N + 15) / 16, 256>>>(bat, b2, N);     // + self-clean acc2, degi
    divide_kernel<<<(G * OUT_C + 255) / 256, 256>>>((float*)d_out, G);  // + self-clean gsum, gcnt
}

// round 17
// speedup vs baseline: 1.1040x; 1.1040x over previous
#include <cuda_runtime.h>
#include <cuda_fp16.h>
#include <mma.h>
#include <cstddef>
#include <cstdint>

using namespace nvcuda;

#define N_NODES   50000
#define N_GRAPHS  128
#define IN_C      128
#define HID_C     128
#define OUT_C     64

// ---------------- device scratch (no allocations allowed) ----------------
// acc1/acc2 are SEEDED by the GEMM epilogues each call (self-loop term), so they
// never need zeroing. Only degi/gsum/gcnt are zeroed (tiny init kernel).
__device__ int    g_degi[N_NODES];
__device__ __half g_g1h [(size_t)N_NODES * HID_C];   // fp16 messages L1 (scatter reads)
__device__ __half g_acc1[(size_t)N_NODES * HID_C];   // seeded accumulator L1
__device__ __half g_g2h [(size_t)N_NODES * OUT_C];   // fp16 messages L2 (scatter reads)
__device__ __half g_acc2[(size_t)N_NODES * OUT_C];   // seeded accumulator L2
__device__ float  g_gsum[N_GRAPHS * OUT_C];
__device__ float  g_gcnt[N_GRAPHS];

__device__ __forceinline__ float node_dinv(int i) {
    return rsqrtf((float)(1 + g_degi[i]));   // +1 self-loop
}
__device__ __forceinline__ void red_add_v4(float* p, float4 v) {
    asm volatile("red.global.add.v4.f32 [%0], {%1, %2, %3, %4};"
                 :: "l"(p), "f"(v.x), "f"(v.y), "f"(v.z), "f"(v.w)
                 : "memory");
}
// 8 halfs per op (16B) — sm_90+
__device__ __forceinline__ void red_add_v4h(__half* p, uint4 v) {
    asm volatile("red.global.add.noftz.v4.f16x2 [%0], {%1, %2, %3, %4};"
                 :: "l"(p), "r"(v.x), "r"(v.y), "r"(v.z), "r"(v.w)
                 : "memory");
}
__device__ __forceinline__ uint4 f8_to_h8(float4 a, float4 b) {
    __half2 h0 = __floats2half2_rn(a.x, a.y);
    __half2 h1 = __floats2half2_rn(a.z, a.w);
    __half2 h2 = __floats2half2_rn(b.x, b.y);
    __half2 h3 = __floats2half2_rn(b.z, b.w);
    uint4 u;
    u.x = *reinterpret_cast<unsigned*>(&h0);
    u.y = *reinterpret_cast<unsigned*>(&h1);
    u.z = *reinterpret_cast<unsigned*>(&h2);
    u.w = *reinterpret_cast<unsigned*>(&h3);
    return u;
}

// ---------------- tiny init: zero degi/gsum/gcnt (~230 KB) ----------------
__global__ void init_kernel() {
    int i = blockIdx.x * blockDim.x + threadIdx.x;
    if (i < N_NODES) g_degi[i] = 0;
    if (i < N_GRAPHS * OUT_C) g_gsum[i] = 0.f;
    if (i < N_GRAPHS) g_gcnt[i] = 0.f;
}

// ---------------- degree (by dst) ----------------
__global__ void deg_kernel(const int* __restrict__ dst, int E) {
    int e = blockIdx.x * blockDim.x + threadIdx.x;
    if (e < E) atomicAdd(&g_degi[dst[e]], 1);
}

// ---------------- fp16 HMMA GEMM, BM=64: message = dinv ⊙ (A[M,128] @ B[128,LD]) ----------------
// Writes the message row to BOTH C16 (scatter-readable) and Cseed (accumulator
// seeded with the self-loop term — no zero-init needed).
// 256 threads = 8 warps as 4(m) x 2(n); warp covers 16 rows x LD/2 cols.
// FUSE_IN: A row = relu(dinv*acc1 + bias)  (acc1 already holds self + neighbors).
template<int LD, bool FUSE_IN>
__global__ void __launch_bounds__(256)
hgemm_kernel(const float* __restrict__ A,
             const float* __restrict__ bias,
             const float* __restrict__ B,
             __half* __restrict__ C16,
             __half* __restrict__ Cseed, int M) {
    extern __shared__ __half sm[];
    constexpr int LDA = 136;          // 128 + 8 pad
    constexpr int LDB = LD + 8;
    constexpr int NT  = LD / 32;      // 16-wide n-tiles per warp
    __half* As = sm;                  // [64][136]
    __half* Bs = sm + 64 * LDA;       // [128][LDB]

    const int tid    = threadIdx.x;
    const int wid    = tid >> 5;
    const int lane   = tid & 31;
    const int warp_m = wid >> 1;      // rows warp_m*16
    const int warp_n = wid & 1;       // cols warp_n*(LD/2)
    const int row0   = blockIdx.x * 64;

    // ---- stage A: 64*128 halfs = 1024 chunks of 8; 4 iters ----
#pragma unroll
    for (int it = 0; it < 4; it++) {
        int chunk = tid + it * 256;
        int r  = chunk >> 4;
        int c8 = chunk & 15;
        int grow = row0 + r;
        uint4 u;
        if (grow < M) {
            if (FUSE_IN) {
                float dv = node_dinv(grow);
                uint4 au = ((const uint4*)(g_acc1 + (size_t)grow * 128))[c8];
                float4 bv0 = *(const float4*)(bias + c8 * 8);
                float4 bv1 = *(const float4*)(bias + c8 * 8 + 4);
                const __half2* ah = (const __half2*)&au;
                float4 lo, hi;
                float2 t0 = __half22float2(ah[0]);
                float2 t1 = __half22float2(ah[1]);
                float2 t2 = __half22float2(ah[2]);
                float2 t3 = __half22float2(ah[3]);
                lo.x = fmaxf(dv * t0.x + bv0.x, 0.f);
                lo.y = fmaxf(dv * t0.y + bv0.y, 0.f);
                lo.z = fmaxf(dv * t1.x + bv0.z, 0.f);
                lo.w = fmaxf(dv * t1.y + bv0.w, 0.f);
                hi.x = fmaxf(dv * t2.x + bv1.x, 0.f);
                hi.y = fmaxf(dv * t2.y + bv1.y, 0.f);
                hi.z = fmaxf(dv * t3.x + bv1.z, 0.f);
                hi.w = fmaxf(dv * t3.y + bv1.w, 0.f);
                u = f8_to_h8(lo, hi);
            } else {
                float4 lo = *(const float4*)(A + (size_t)grow * 128 + c8 * 8);
                float4 hi = *(const float4*)(A + (size_t)grow * 128 + c8 * 8 + 4);
                u = f8_to_h8(lo, hi);
            }
        } else {
            u = make_uint4(0, 0, 0, 0);
        }
        *(uint4*)(As + r * LDA + c8 * 8) = u;
    }
    // ---- stage B: 128*LD halfs ----
    constexpr int BCH = 128 * LD / 8 / 256;   // 8 (LD=128) or 4 (LD=64)
#pragma unroll
    for (int it = 0; it < BCH; it++) {
        int chunk = tid + it * 256;
        int r  = chunk / (LD / 8);
        int c8 = chunk % (LD / 8);
        float4 lo = *(const float4*)(B + (size_t)r * LD + c8 * 8);
        float4 hi = *(const float4*)(B + (size_t)r * LD + c8 * 8 + 4);
        *(uint4*)(Bs + r * LDB + c8 * 8) = f8_to_h8(lo, hi);
    }
    __syncthreads();

    // ---- MMA: 8 k-steps, 1 m-frag x NT n-frags per warp ----
    wmma::fragment<wmma::accumulator, 16, 16, 16, float> acc[NT];
#pragma unroll
    for (int nt = 0; nt < NT; nt++) wmma::fill_fragment(acc[nt], 0.f);

#pragma unroll
    for (int k = 0; k < 8; k++) {
        wmma::fragment<wmma::matrix_a, 16, 16, 16, __half, wmma::row_major> a0;
        wmma::load_matrix_sync(a0, As + (warp_m * 16) * LDA + k * 16, LDA);
#pragma unroll
        for (int nt = 0; nt < NT; nt++) {
            wmma::fragment<wmma::matrix_b, 16, 16, 16, __half, wmma::row_major> b;
            wmma::load_matrix_sync(b, Bs + (k * 16) * LDB + warp_n * (LD / 2) + nt * 16, LDB);
            wmma::mma_sync(acc[nt], a0, b, acc[nt]);
        }
    }
    __syncthreads();

    // ---- epilogue: per-warp staging (ldm=16 — WMMA contract), dinv, dual fp16 store ----
    float* wbuf = (float*)(sm) + wid * 256;    // 16x16 floats per warp
#pragma unroll
    for (int nt = 0; nt < NT; nt++) {
        wmma::store_matrix_sync(wbuf, acc[nt], 16, wmma::mem_row_major);
        __syncwarp();
        int r  = lane >> 1;
        int c8 = (lane & 1) * 8;
        int grow = row0 + warp_m * 16 + r;
        if (grow < M) {
            float d = node_dinv(grow);
            const float* p = wbuf + r * 16 + c8;
            float4 lo = make_float4(d * p[0], d * p[1], d * p[2], d * p[3]);
            float4 hi = make_float4(d * p[4], d * p[5], d * p[6], d * p[7]);
            int col = warp_n * (LD / 2) + nt * 16 + c8;
            uint4 u = f8_to_h8(lo, hi);
            *(uint4*)(C16   + (size_t)grow * LD + col) = u;   // message (scatter reads)
            *(uint4*)(Cseed + (size_t)grow * LD + col) = u;   // accumulator seed (self term)
        }
        __syncwarp();
    }
}

// ---------------- scatter layer 1: acc1[dst] += g1h[src] (128 halfs/edge, 16 lanes) ----------------
__global__ void scatter1_kernel(const int* __restrict__ src,
                                const int* __restrict__ dst,
                                int E) {
    int t = blockIdx.x * blockDim.x + threadIdx.x;
    int e = t >> 4;
    int lane = t & 15;
    if (e >= E) return;
    int s = src[e];
    int d = dst[e];
    uint4 v = ((const uint4*)(g_g1h + (size_t)s * HID_C))[lane];  // 8 halfs
    red_add_v4h(g_acc1 + (size_t)d * HID_C + lane * 8, v);
}

// ---------------- scatter layer 2: acc2[dst] += g2h[src] (64 halfs/edge, 8 lanes) ----------------
__global__ void scatter2_kernel(const int* __restrict__ src,
                                const int* __restrict__ dst,
                                int E) {
    int t = blockIdx.x * blockDim.x + threadIdx.x;
    int e = t >> 3;
    int lane = t & 7;
    if (e >= E) return;
    int s = src[e];
    int d = dst[e];
    uint4 v = ((const uint4*)(g_g2h + (size_t)s * OUT_C))[lane];  // 8 halfs
    red_add_v4h(g_acc2 + (size_t)d * OUT_C + lane * 8, v);
}

// ---------------- pool: out2 = dinv*acc2 + b2; RED into graph sums ----------------
__global__ void pool_kernel(const int* __restrict__ batch,
                            const float* __restrict__ b2,
                            int N) {
    int t = blockIdx.x * blockDim.x + threadIdx.x;
    int node = t >> 4;
    int lane = t & 15;
    if (node >= N) return;
    int b = batch[node];
    float dv = node_dinv(node);
    uint2 au = ((const uint2*)(g_acc2 + (size_t)node * OUT_C))[lane];
    __half2 ah0 = *reinterpret_cast<__half2*>(&au.x);
    __half2 ah1 = *reinterpret_cast<__half2*>(&au.y);
    float2 a0 = __half22float2(ah0), a1 = __half22float2(ah1);
    float4 bv = *(const float4*)(b2 + lane * 4);
    float4 r;
    r.x = dv * a0.x + bv.x;
    r.y = dv * a0.y + bv.y;
    r.z = dv * a1.x + bv.z;
    r.w = dv * a1.y + bv.w;
    red_add_v4(g_gsum + b * OUT_C + lane * 4, r);
    if (lane == 0) atomicAdd(&g_gcnt[b], 1.0f);
}

__global__ void divide_kernel(float* __restrict__ out, int G) {
    int i = blockIdx.x * blockDim.x + threadIdx.x;
    if (i < G * OUT_C) {
        float c = g_gcnt[i / OUT_C];
        out[i] = g_gsum[i] / fmaxf(c, 1.0f);
    }
}

// ---------------- launch ----------------
extern "C" void kernel_launch(void* const* d_in, const int* in_sizes, int n_in,
                              void* d_out, int out_size) {
    const float* x   = (const float*)d_in[0];
    const float* W1  = (const float*)d_in[1];
    const float* b1  = (const float*)d_in[2];
    const float* W2  = (const float*)d_in[3];
    const float* b2  = (const float*)d_in[4];
    const int*   ei  = (const int*)d_in[5];   // int32
    const int*   bat = (const int*)d_in[6];

    const int N = in_sizes[0] / IN_C;      // 50000
    const int E = in_sizes[5] / 2;         // 625000
    const int G = out_size / OUT_C;        // 128

    const int* src = ei;
    const int* dst = ei + E;

    void *p_g1h, *p_g2h, *p_acc1, *p_acc2;
    cudaGetSymbolAddress(&p_g1h,  g_g1h);
    cudaGetSymbolAddress(&p_g2h,  g_g2h);
    cudaGetSymbolAddress(&p_acc1, g_acc1);
    cudaGetSymbolAddress(&p_acc2, g_acc2);

    init_kernel<<<(N + 255) / 256, 256>>>();            // degi/gsum/gcnt only (~230 KB)
    deg_kernel <<<(E + 255) / 256, 256>>>(dst, E);

    // GEMM1: g1h = acc1_seed = dinv * (x @ W1)
    {
        const int smem = (64 * 136 + 128 * (128 + 8)) * (int)sizeof(__half);
        cudaFuncSetAttribute(hgemm_kernel<128, false>,
                             cudaFuncAttributeMaxDynamicSharedMemorySize, smem);
        hgemm_kernel<128, false><<<(N + 63) / 64, 256, smem>>>(
            x, nullptr, W1, (__half*)p_g1h, (__half*)p_acc1, N);
    }
    scatter1_kernel<<<((size_t)E * 16 + 255) / 256, 256>>>(src, dst, E);

    // GEMM2: g2h = acc2_seed = dinv * (relu(dinv*acc1 + b1) @ W2)
    {
        const int smem = (64 * 136 + 128 * (64 + 8)) * (int)sizeof(__half);
        cudaFuncSetAttribute(hgemm_kernel<64, true>,
                             cudaFuncAttributeMaxDynamicSharedMemorySize, smem);
        hgemm_kernel<64, true><<<(N + 63) / 64, 256, smem>>>(
            nullptr, b1, W2, (__half*)p_g2h, (__half*)p_acc2, N);
    }
    scatter2_kernel<<<((size_t)E * 8 + 255) / 256, 256>>>(src, dst, E);

    pool_kernel<<<(N + 15) / 16, 256>>>(bat, b2, N);
    divide_kernel<<<(G * OUT_C + 255) / 256, 256>>>((float*)d_out, G);
}